// round 14
// baseline (speedup 1.0000x reference)
#include <cuda_runtime.h>
#include <cuda_bf16.h>
#include <cstdint>

#define N_PTS   8192
#define DIM     128
#define NTILE   64                 // 8192 / 128
#define TRI     ((NTILE * (NTILE + 1)) / 2)   // 2080 tile-pairs
#define GRID_MAIN 148
#define MARGIN  0.3f
#define BIGF    1e30f
#define NTHREADS 512
#define FIN_BLOCKS 16

// ---------------- device scratch ----------------
__device__ __align__(128) int   g_lab[N_PTS];
__device__ __align__(128) float g_sq[N_PTS];
__device__ int   g_pos[N_PTS];                       // float bits of hardest-pos d^2
__device__ int   g_neg[N_PTS];                       // float bits of hardest-neg d^2
__device__ int   g_done;
__device__ float g_sum, g_cnt;
__device__ __align__(256) unsigned short g_hi[N_PTS * DIM];
__device__ __align__(256) unsigned short g_lo[N_PTS * DIM];

// smem: A (hi+lo) @0 (64K), B double buffer @65536 (2x64K), meta 4-slot ring @196608
#define SM_A      0
#define SM_B      65536
#define SM_META   196608
#define SM_TOTAL  200704

// ---------------- PTX helpers (base sm_80+ ISA only) ----------------
__device__ __forceinline__ uint32_t smem_u32(const void* p) {
    uint32_t a;
    asm("{ .reg .u64 t; cvta.to.shared.u64 t, %1; cvt.u32.u64 %0, t; }" : "=r"(a) : "l"(p));
    return a;
}
__device__ __forceinline__ void cp_async16(uint32_t dst, const void* src) {
    asm volatile("cp.async.cg.shared.global [%0], [%1], 16;" :: "r"(dst), "l"(src) : "memory");
}
__device__ __forceinline__ void cp_commit() { asm volatile("cp.async.commit_group;" ::: "memory"); }
template <int N>
__device__ __forceinline__ void cp_wait() { asm volatile("cp.async.wait_group %0;" :: "n"(N) : "memory"); }

__device__ __forceinline__ void ldsm4(uint32_t* r, uint32_t addr) {
    asm volatile("ldmatrix.sync.aligned.m8n8.x4.shared.b16 {%0,%1,%2,%3}, [%4];"
                 : "=r"(r[0]), "=r"(r[1]), "=r"(r[2]), "=r"(r[3]) : "r"(addr));
}
__device__ __forceinline__ void mma_bf16(float* d, const uint32_t* a, uint32_t b0, uint32_t b1) {
    asm volatile("mma.sync.aligned.m16n8k16.row.col.f32.bf16.bf16.f32 "
                 "{%0,%1,%2,%3}, {%4,%5,%6,%7}, {%8,%9}, {%0,%1,%2,%3};"
                 : "+f"(d[0]), "+f"(d[1]), "+f"(d[2]), "+f"(d[3])
                 : "r"(a[0]), "r"(a[1]), "r"(a[2]), "r"(a[3]), "r"(b0), "r"(b1));
}

// ---------------- prep: detect + norms + labels + sentinels + hi/lo split ----
__global__ void prep_kernel(const float* __restrict__ emb, const int* __restrict__ l32) {
    int warp = (blockIdx.x * blockDim.x + threadIdx.x) >> 5;
    int lane = threadIdx.x & 31;

    // int64-vs-int32 detection: fixed window, identical verdict in every warp.
    unsigned oddw = (unsigned)l32[2 * lane + 1];
    unsigned ball = __ballot_sync(0xFFFFFFFFu, oddw != 0);
    int mode64 = (ball == 0);

    const float4* row = (const float4*)(emb + (size_t)warp * DIM);
    float4 v = row[lane];
    float s = v.x * v.x + v.y * v.y + v.z * v.z + v.w * v.w;
    #pragma unroll
    for (int m = 16; m; m >>= 1) s += __shfl_xor_sync(0xFFFFFFFFu, s, m);

    __nv_bfloat16 h0 = __float2bfloat16_rn(v.x), h1 = __float2bfloat16_rn(v.y);
    __nv_bfloat16 h2 = __float2bfloat16_rn(v.z), h3 = __float2bfloat16_rn(v.w);
    __nv_bfloat16 l0 = __float2bfloat16_rn(v.x - __bfloat162float(h0));
    __nv_bfloat16 l1 = __float2bfloat16_rn(v.y - __bfloat162float(h1));
    __nv_bfloat16 l2 = __float2bfloat16_rn(v.z - __bfloat162float(h2));
    __nv_bfloat16 l3 = __float2bfloat16_rn(v.w - __bfloat162float(h3));
    ((ushort4*)(g_hi + (size_t)warp * DIM))[lane] =
        make_ushort4(__bfloat16_as_ushort(h0), __bfloat16_as_ushort(h1),
                     __bfloat16_as_ushort(h2), __bfloat16_as_ushort(h3));
    ((ushort4*)(g_lo + (size_t)warp * DIM))[lane] =
        make_ushort4(__bfloat16_as_ushort(l0), __bfloat16_as_ushort(l1),
                     __bfloat16_as_ushort(l2), __bfloat16_as_ushort(l3));

    if (lane == 0) {
        g_sq[warp]  = s;
        g_lab[warp] = mode64 ? l32[2 * warp] : l32[warp];
        g_pos[warp] = __float_as_int(-1.0f);
        g_neg[warp] = __float_as_int(BIGF);
    }
    if (warp == 0 && lane == 0) { g_done = 0; g_sum = 0.0f; g_cnt = 0.0f; }
}

// ---------------- main fused GEMM + two-sided mining ----------------
extern __shared__ unsigned char smem[];

__device__ __forceinline__ void load_tileA(uint32_t dst, int rowBase, int tid) {
    #pragma unroll
    for (int it = 0; it < 8; it++) {
        int u   = it * NTHREADS + tid;
        int tau = u >> 11;                 // 0: hi, 1: lo
        int r   = (u >> 4) & 127;
        int c   = u & 15;
        const unsigned short* src = (tau ? g_lo : g_hi) + (size_t)(rowBase + r) * DIM + c * 8;
        cp_async16(dst + tau * 32768 + r * 256 + ((c ^ (r & 7)) << 4), src);
    }
}
__device__ __forceinline__ void load_tileB(uint32_t dst, uint32_t mOff, int slot, int rowBase, int tid) {
    load_tileA(dst, rowBase, tid);
    uint32_t metaDst = mOff + (uint32_t)slot * 1024;
    if (tid < 32)
        cp_async16(metaDst + tid * 16, (const char*)g_sq + (size_t)rowBase * 4 + tid * 16);
    else if (tid < 64)
        cp_async16(metaDst + 512 + (tid - 32) * 16, (const char*)g_lab + (size_t)rowBase * 4 + (tid - 32) * 16);
}

__global__ void __launch_bounds__(NTHREADS, 1) main_kernel() {
    const int tid  = threadIdx.x;
    const int lane = tid & 31;
    const int wid  = tid >> 5;
    const int wx   = wid & 3;              // n: 4 warps x 32 cols
    const int wy   = wid >> 2;             // m: 4 warps x 32 rows

    uint32_t sb = smem_u32(smem);
    const uint32_t A_OFF = sb + SM_A;
    const uint32_t B_OFF = sb + SM_B;
    const uint32_t M_OFF = sb + SM_META;

    const int rsel = lane & 15;
    const int ksel = (lane >> 4) & 1;
    uint32_t aRel[2]; int a7[2];
    #pragma unroll
    for (int mb = 0; mb < 2; mb++) {
        int r = wy * 32 + mb * 16 + rsel;
        aRel[mb] = (uint32_t)(r * 256); a7[mb] = r & 7;
    }
    uint32_t bOffs[2]; int b7[2];
    #pragma unroll
    for (int g = 0; g < 2; g++) {
        int n = wx * 32 + g * 16 + rsel;
        bOffs[g] = (uint32_t)(n * 256); b7[g] = n & 7;
    }

    // triangular schedule: CTA gets tiles [start, end) of TRI, row-major
    const int start = (int)(((long)blockIdx.x * TRI) / gridDim.x);
    const int end   = (int)(((long)(blockIdx.x + 1) * TRI) / gridDim.x);
    int ti = 0, rem = start;
    while (rem >= NTILE - ti) { rem -= NTILE - ti; ti++; }
    int tj0 = ti + rem;
    int w = start;

    #pragma unroll 1
    while (w < end) {
        const int len   = min(NTILE - tj0, end - w);
        const int iBase = ti * 128;

        // row metadata + mining state for this segment
        int labi[4]; float sqi[4]; float pmm[4], nmm[4];
        #pragma unroll
        for (int mb = 0; mb < 2; mb++) {
            int r0 = iBase + wy * 32 + mb * 16 + (lane >> 2);
            labi[mb * 2 + 0] = g_lab[r0];     sqi[mb * 2 + 0] = g_sq[r0];
            labi[mb * 2 + 1] = g_lab[r0 + 8]; sqi[mb * 2 + 1] = g_sq[r0 + 8];
            pmm[mb * 2] = -BIGF; pmm[mb * 2 + 1] = -BIGF;
            nmm[mb * 2] =  BIGF; nmm[mb * 2 + 1] =  BIGF;
        }

        // segment prologue: A, B0(+meta slot0), B1(+meta slot1)
        load_tileA(A_OFF, iBase, tid);                               cp_commit();
        load_tileB(B_OFF,         M_OFF, 0, tj0 * 128, tid);         cp_commit();
        if (len > 1) {
            load_tileB(B_OFF + 65536, M_OFF, 1, (tj0 + 1) * 128, tid);
            cp_commit();
            cp_wait<1>();                  // A + B0 resident, B1 in flight
        } else {
            cp_wait<0>();
        }
        __syncthreads();

        #pragma unroll 1
        for (int t = 0; t < len; t++) {
            const uint32_t bufB = B_OFF + (t & 1) * 65536;
            const int jBase = (tj0 + t) * 128;

            float acc[2][4][4];
            #pragma unroll
            for (int mb = 0; mb < 2; mb++)
                #pragma unroll
                for (int nb = 0; nb < 4; nb++)
                    #pragma unroll
                    for (int e = 0; e < 4; e++) acc[mb][nb][e] = 0.0f;

            // ---- product-outer mainloop with double-buffered fragments.
            // Pass 0: Ah*Bh, pass 1: Ah*Bl, pass 2: Al*Bh. Per kc only 16
            // frag regs are consumed, so the other 16 hold kc+1's prefetch:
            // ldsm(kc+1) overlaps the 8 independent MMAs of kc.
            #pragma unroll
            for (int p = 0; p < 3; p++) {
                const uint32_t aT = A_OFF + ((p == 2) ? 32768u : 0u);
                const uint32_t bT = bufB  + ((p == 1) ? 32768u : 0u);
                uint32_t af[2][2][4], bf[2][2][4];   // [buf][mb|g][frag]
                {
                    const int chunk0 = ksel;
                    #pragma unroll
                    for (int mb = 0; mb < 2; mb++)
                        ldsm4(af[0][mb], aT + aRel[mb] + (uint32_t)((chunk0 ^ a7[mb]) << 4));
                    #pragma unroll
                    for (int g = 0; g < 2; g++)
                        ldsm4(bf[0][g], bT + bOffs[g] + (uint32_t)((chunk0 ^ b7[g]) << 4));
                }
                #pragma unroll
                for (int kc = 0; kc < 8; kc++) {
                    const int cur = kc & 1, nxt = cur ^ 1;
                    if (kc < 7) {
                        const int chunk = (kc + 1) * 2 + ksel;
                        #pragma unroll
                        for (int mb = 0; mb < 2; mb++)
                            ldsm4(af[nxt][mb], aT + aRel[mb] + (uint32_t)((chunk ^ a7[mb]) << 4));
                        #pragma unroll
                        for (int g = 0; g < 2; g++)
                            ldsm4(bf[nxt][g], bT + bOffs[g] + (uint32_t)((chunk ^ b7[g]) << 4));
                    }
                    #pragma unroll
                    for (int mb = 0; mb < 2; mb++)
                        #pragma unroll
                        for (int g = 0; g < 2; g++) {
                            mma_bf16(acc[mb][g * 2 + 0], af[cur][mb], bf[cur][g][0], bf[cur][g][2]);
                            mma_bf16(acc[mb][g * 2 + 1], af[cur][mb], bf[cur][g][1], bf[cur][g][3]);
                        }
                }
            }

            // ---- two-sided mining epilogue. Meta read straight from the
            // 4-slot ring: the only writer during this window targets slot
            // (t+2)&3 (issued after the barrier below), distance 2 from t&3.
            const unsigned char* metaS = smem + SM_META + ((t & 3) * 1024);
            #pragma unroll
            for (int nb = 0; nb < 4; nb++) {
                int idx = wx * 32 + nb * 8 + (lane & 3) * 2;
                float2 sq2  = *(const float2*)(metaS + idx * 4);
                int2   lab2 = *(const int2*)(metaS + 512 + idx * 4);
                float cp0 = -BIGF, cn0 = BIGF, cp1 = -BIGF, cn1 = BIGF;
                #pragma unroll
                for (int mb = 0; mb < 2; mb++) {
                    const int h0 = mb * 2, h1 = mb * 2 + 1;
                    float m00 = fmaf(acc[mb][nb][0], -2.0f, sq2.x);
                    float m01 = fmaf(acc[mb][nb][1], -2.0f, sq2.y);
                    float m10 = fmaf(acc[mb][nb][2], -2.0f, sq2.x);
                    float m11 = fmaf(acc[mb][nb][3], -2.0f, sq2.y);
                    bool e00 = (lab2.x == labi[h0]);
                    bool e01 = (lab2.y == labi[h0]);
                    bool e10 = (lab2.x == labi[h1]);
                    bool e11 = (lab2.y == labi[h1]);
                    if (e00) pmm[h0] = fmaxf(pmm[h0], m00); else nmm[h0] = fminf(nmm[h0], m00);
                    if (e01) pmm[h0] = fmaxf(pmm[h0], m01); else nmm[h0] = fminf(nmm[h0], m01);
                    if (e10) pmm[h1] = fmaxf(pmm[h1], m10); else nmm[h1] = fminf(nmm[h1], m10);
                    if (e11) pmm[h1] = fmaxf(pmm[h1], m11); else nmm[h1] = fminf(nmm[h1], m11);
                    float d00 = m00 + sqi[h0], d01 = m01 + sqi[h0];
                    float d10 = m10 + sqi[h1], d11 = m11 + sqi[h1];
                    if (e00) cp0 = fmaxf(cp0, d00); else cn0 = fminf(cn0, d00);
                    if (e01) cp1 = fmaxf(cp1, d01); else cn1 = fminf(cn1, d01);
                    if (e10) cp0 = fmaxf(cp0, d10); else cn0 = fminf(cn0, d10);
                    if (e11) cp1 = fmaxf(cp1, d11); else cn1 = fminf(cn1, d11);
                }
                #pragma unroll
                for (int m = 4; m <= 16; m <<= 1) {
                    cp0 = fmaxf(cp0, __shfl_xor_sync(0xFFFFFFFFu, cp0, m));
                    cn0 = fminf(cn0, __shfl_xor_sync(0xFFFFFFFFu, cn0, m));
                    cp1 = fmaxf(cp1, __shfl_xor_sync(0xFFFFFFFFu, cp1, m));
                    cn1 = fminf(cn1, __shfl_xor_sync(0xFFFFFFFFu, cn1, m));
                }
                if (lane < 4) {
                    int j0 = jBase + wx * 32 + nb * 8 + lane * 2;
                    atomicMax(&g_pos[j0],     __float_as_int(cp0));
                    atomicMin(&g_neg[j0],     __float_as_int(cn0));
                    atomicMax(&g_pos[j0 + 1], __float_as_int(cp1));
                    atomicMin(&g_neg[j0 + 1], __float_as_int(cn1));
                }
            }

            // ---- single sync point per tile:
            //  * my prior cp.async groups (B[t+1]+meta) are complete
            //  * barrier makes them visible AND retires everyone's B[t] reads
            //  * then overwrite buf[t&1] with B[t+2]
            if (t + 1 < len) {
                cp_wait<0>();
                __syncthreads();
                if (t + 2 < len) {
                    load_tileB(B_OFF + (t & 1) * 65536, M_OFF, (t + 2) & 3,
                               (tj0 + t + 2) * 128, tid);
                    cp_commit();
                }
            }
        }
        __syncthreads();                   // smem quiescent before next segment

        // row-side flush for this segment
        #pragma unroll
        for (int mb = 0; mb < 2; mb++) {
            #pragma unroll
            for (int h = 0; h < 2; h++) {
                int q = mb * 2 + h;
                float p = sqi[q] + pmm[q];
                float n = sqi[q] + nmm[q];
                p = fmaxf(p, __shfl_xor_sync(0xFFFFFFFFu, p, 1));
                p = fmaxf(p, __shfl_xor_sync(0xFFFFFFFFu, p, 2));
                n = fminf(n, __shfl_xor_sync(0xFFFFFFFFu, n, 1));
                n = fminf(n, __shfl_xor_sync(0xFFFFFFFFu, n, 2));
                if ((lane & 3) == 0) {
                    int row = iBase + wy * 32 + mb * 16 + (lane >> 2) + h * 8;
                    atomicMax(&g_pos[row], __float_as_int(p));
                    atomicMin(&g_neg[row], __float_as_int(n));
                }
            }
        }

        w += len; ti++; tj0 = ti;
    }
}

// ---------------- final reduction: FIN_BLOCKS x 512, atomic partials ----------
__global__ void final_kernel(float* __restrict__ out) {
    int tid = threadIdx.x, lane = tid & 31, wrp = tid >> 5;
    int i = blockIdx.x * 512 + tid;            // 16 * 512 = 8192, one elem each
    float s = 0.0f, c = 0.0f;
    float p = __int_as_float(g_pos[i]);
    float n = __int_as_float(g_neg[i]);
    if (p > 1e-2f && n < 1e29f) {
        s = fmaxf(sqrtf(p) - sqrtf(fmaxf(n, 0.0f)) + MARGIN, 0.0f);
        c = 1.0f;
    }
    #pragma unroll
    for (int m = 16; m; m >>= 1) {
        s += __shfl_xor_sync(0xFFFFFFFFu, s, m);
        c += __shfl_xor_sync(0xFFFFFFFFu, c, m);
    }
    __shared__ float red[32];
    if (lane == 0) { red[wrp] = s; red[16 + wrp] = c; }
    __syncthreads();
    if (wrp == 0) {
        s = (lane < 16) ? red[lane] : 0.0f;
        c = (lane < 16) ? red[16 + lane] : 0.0f;
        #pragma unroll
        for (int m = 8; m; m >>= 1) {
            s += __shfl_xor_sync(0xFFFFFFFFu, s, m);
            c += __shfl_xor_sync(0xFFFFFFFFu, c, m);
        }
        if (lane == 0) {
            atomicAdd(&g_sum, s);
            atomicAdd(&g_cnt, c);
            __threadfence();
            if (atomicAdd(&g_done, 1) == FIN_BLOCKS - 1) {
                float S = atomicAdd(&g_sum, 0.0f);
                float C = atomicAdd(&g_cnt, 0.0f);
                out[0] = (C > 0.0f) ? (S / C) : 0.0f;
            }
        }
    }
}

// ---------------- launch ----------------
extern "C" void kernel_launch(void* const* d_in, const int* in_sizes, int n_in,
                              void* d_out, int out_size) {
    const float* emb = (const float*)d_in[0];
    const int*   lab = (const int*)d_in[1];

    cudaFuncSetAttribute(main_kernel, cudaFuncAttributeMaxDynamicSharedMemorySize, SM_TOTAL);

    prep_kernel<<<N_PTS * 32 / 256, 256>>>(emb, lab);
    main_kernel<<<GRID_MAIN, NTHREADS, SM_TOTAL>>>();
    final_kernel<<<FIN_BLOCKS, 512>>>((float*)d_out);
}

// round 15
// speedup vs baseline: 1.5185x; 1.5185x over previous
#include <cuda_runtime.h>
#include <cuda_bf16.h>
#include <cstdint>

#define N_PTS   8192
#define DIM     128
#define BT      64                  // tile edge
#define NTILE   128                 // 8192 / 64
#define TRI     (NTILE * (NTILE + 1) / 2)   // 8256 tile-pairs
#define GRID_MAIN 296               // 148 SMs x 2 CTAs
#define MARGIN  0.3f
#define BIGF    1e30f
#define NTHREADS 256
#define FIN_BLOCKS 16

// ---------------- device scratch ----------------
__device__ __align__(128) int   g_lab[N_PTS];
__device__ __align__(128) float g_sq[N_PTS];
__device__ int   g_pos[N_PTS];
__device__ int   g_neg[N_PTS];
__device__ int   g_done;
__device__ float g_sum, g_cnt;
__device__ __align__(256) unsigned short g_hi[N_PTS * DIM];
__device__ __align__(256) unsigned short g_lo[N_PTS * DIM];

// smem: A (hi+lo) 32K @0, B double buffer 2x32K @32768, meta 4-slot ring @98304
#define SM_A      0
#define SM_B      32768
#define SM_META   98304
#define SM_TOTAL  100352

// ---------------- PTX helpers (base sm_80+ ISA only) ----------------
__device__ __forceinline__ uint32_t smem_u32(const void* p) {
    uint32_t a;
    asm("{ .reg .u64 t; cvta.to.shared.u64 t, %1; cvt.u32.u64 %0, t; }" : "=r"(a) : "l"(p));
    return a;
}
__device__ __forceinline__ void cp_async16(uint32_t dst, const void* src) {
    asm volatile("cp.async.cg.shared.global [%0], [%1], 16;" :: "r"(dst), "l"(src) : "memory");
}
__device__ __forceinline__ void cp_commit() { asm volatile("cp.async.commit_group;" ::: "memory"); }
template <int N>
__device__ __forceinline__ void cp_wait() { asm volatile("cp.async.wait_group %0;" :: "n"(N) : "memory"); }

__device__ __forceinline__ void ldsm4(uint32_t* r, uint32_t addr) {
    asm volatile("ldmatrix.sync.aligned.m8n8.x4.shared.b16 {%0,%1,%2,%3}, [%4];"
                 : "=r"(r[0]), "=r"(r[1]), "=r"(r[2]), "=r"(r[3]) : "r"(addr));
}
__device__ __forceinline__ void mma_bf16(float* d, const uint32_t* a, uint32_t b0, uint32_t b1) {
    asm volatile("mma.sync.aligned.m16n8k16.row.col.f32.bf16.bf16.f32 "
                 "{%0,%1,%2,%3}, {%4,%5,%6,%7}, {%8,%9}, {%0,%1,%2,%3};"
                 : "+f"(d[0]), "+f"(d[1]), "+f"(d[2]), "+f"(d[3])
                 : "r"(a[0]), "r"(a[1]), "r"(a[2]), "r"(a[3]), "r"(b0), "r"(b1));
}

// ---------------- prep: detect + norms + labels + sentinels + hi/lo split ----
__global__ void prep_kernel(const float* __restrict__ emb, const int* __restrict__ l32) {
    int warp = (blockIdx.x * blockDim.x + threadIdx.x) >> 5;
    int lane = threadIdx.x & 31;

    unsigned oddw = (unsigned)l32[2 * lane + 1];
    unsigned ball = __ballot_sync(0xFFFFFFFFu, oddw != 0);
    int mode64 = (ball == 0);

    const float4* row = (const float4*)(emb + (size_t)warp * DIM);
    float4 v = row[lane];
    float s = v.x * v.x + v.y * v.y + v.z * v.z + v.w * v.w;
    #pragma unroll
    for (int m = 16; m; m >>= 1) s += __shfl_xor_sync(0xFFFFFFFFu, s, m);

    __nv_bfloat16 h0 = __float2bfloat16_rn(v.x), h1 = __float2bfloat16_rn(v.y);
    __nv_bfloat16 h2 = __float2bfloat16_rn(v.z), h3 = __float2bfloat16_rn(v.w);
    __nv_bfloat16 l0 = __float2bfloat16_rn(v.x - __bfloat162float(h0));
    __nv_bfloat16 l1 = __float2bfloat16_rn(v.y - __bfloat162float(h1));
    __nv_bfloat16 l2 = __float2bfloat16_rn(v.z - __bfloat162float(h2));
    __nv_bfloat16 l3 = __float2bfloat16_rn(v.w - __bfloat162float(h3));
    ((ushort4*)(g_hi + (size_t)warp * DIM))[lane] =
        make_ushort4(__bfloat16_as_ushort(h0), __bfloat16_as_ushort(h1),
                     __bfloat16_as_ushort(h2), __bfloat16_as_ushort(h3));
    ((ushort4*)(g_lo + (size_t)warp * DIM))[lane] =
        make_ushort4(__bfloat16_as_ushort(l0), __bfloat16_as_ushort(l1),
                     __bfloat16_as_ushort(l2), __bfloat16_as_ushort(l3));

    if (lane == 0) {
        g_sq[warp]  = s;
        g_lab[warp] = mode64 ? l32[2 * warp] : l32[warp];
        g_pos[warp] = __float_as_int(-1.0f);
        g_neg[warp] = __float_as_int(BIGF);
    }
    if (warp == 0 && lane == 0) { g_done = 0; g_sum = 0.0f; g_cnt = 0.0f; }
}

// ---------------- main fused GEMM + two-sided mining (64x64 tiles) ----------
extern __shared__ unsigned char smem[];

// 64-row tile (hi+lo), 2048 x 16B chunks, swizzle [row][chunk ^ (row&7)]
__device__ __forceinline__ void load_tile(uint32_t dst, int rowBase, int tid) {
    #pragma unroll
    for (int it = 0; it < 8; it++) {
        int u   = it * NTHREADS + tid;
        int tau = u >> 10;                 // 0: hi, 1: lo
        int r   = (u >> 4) & 63;
        int c   = u & 15;
        const unsigned short* src = (tau ? g_lo : g_hi) + (size_t)(rowBase + r) * DIM + c * 8;
        cp_async16(dst + tau * 16384 + r * 256 + ((c ^ (r & 7)) << 4), src);
    }
}
__device__ __forceinline__ void load_tileB(uint32_t dst, uint32_t mOff, int slot, int rowBase, int tid) {
    load_tile(dst, rowBase, tid);
    uint32_t metaDst = mOff + (uint32_t)slot * 512;
    if (tid < 16)
        cp_async16(metaDst + tid * 16, (const char*)g_sq + (size_t)rowBase * 4 + tid * 16);
    else if (tid < 32)
        cp_async16(metaDst + 256 + (tid - 16) * 16, (const char*)g_lab + (size_t)rowBase * 4 + (tid - 16) * 16);
}

__global__ void __launch_bounds__(NTHREADS, 2) main_kernel() {
    const int tid  = threadIdx.x;
    const int lane = tid & 31;
    const int wid  = tid >> 5;
    const int wy   = wid & 1;              // m: 2 warps x 32 rows = 64
    const int wx   = wid >> 1;             // n: 4 warps x 16 cols = 64

    uint32_t sb = smem_u32(smem);
    const uint32_t A_OFF = sb + SM_A;
    const uint32_t B_OFF = sb + SM_B;
    const uint32_t M_OFF = sb + SM_META;

    const int rsel = lane & 15;
    const int ksel = (lane >> 4) & 1;
    uint32_t aRel[2]; int a7[2];
    #pragma unroll
    for (int mb = 0; mb < 2; mb++) {
        int r = wy * 32 + mb * 16 + rsel;
        aRel[mb] = (uint32_t)(r * 256); a7[mb] = r & 7;
    }
    const int nsel = wx * 16 + rsel;
    const uint32_t bOff = (uint32_t)(nsel * 256);
    const int b7 = nsel & 7;

    // paired super-row schedule: super-row sr pairs row sr (len 128-sr)
    // with row 127-sr (len sr+1): constant 129 tiles per super-row.
    const int start = (int)(((long)blockIdx.x * TRI) / gridDim.x);
    const int end   = (int)(((long)(blockIdx.x + 1) * TRI) / gridDim.x);
    int f = start;

    #pragma unroll 1
    while (f < end) {
        const int sr = f / 129;
        const int o  = f - sr * 129;
        int ti, tj0, rowEnd;
        if (o < 128 - sr) { ti = sr;       tj0 = sr + o; rowEnd = 128 - sr; }
        else              { ti = 127 - sr; tj0 = o - 1;  rowEnd = 129; }
        const int len   = min(rowEnd - o, end - f);
        const int iBase = ti * BT;

        // row metadata + mining state for this segment
        int labi[4]; float sqi[4]; float pmm[4], nmm[4];
        #pragma unroll
        for (int mb = 0; mb < 2; mb++) {
            int r0 = iBase + wy * 32 + mb * 16 + (lane >> 2);
            labi[mb * 2 + 0] = g_lab[r0];     sqi[mb * 2 + 0] = g_sq[r0];
            labi[mb * 2 + 1] = g_lab[r0 + 8]; sqi[mb * 2 + 1] = g_sq[r0 + 8];
            pmm[mb * 2] = -BIGF; pmm[mb * 2 + 1] = -BIGF;
            nmm[mb * 2] =  BIGF; nmm[mb * 2 + 1] =  BIGF;
        }

        // segment prologue
        load_tile(A_OFF, iBase, tid);                            cp_commit();
        load_tileB(B_OFF,         M_OFF, 0, tj0 * BT, tid);      cp_commit();
        if (len > 1) {
            load_tileB(B_OFF + 32768, M_OFF, 1, (tj0 + 1) * BT, tid);
            cp_commit();
            cp_wait<1>();
        } else {
            cp_wait<0>();
        }
        __syncthreads();

        #pragma unroll 1
        for (int t = 0; t < len; t++) {
            const uint32_t bufB = B_OFF + (t & 1) * 32768;
            const int jBase = (tj0 + t) * BT;

            float acc[2][2][4];
            #pragma unroll
            for (int mb = 0; mb < 2; mb++)
                #pragma unroll
                for (int nb = 0; nb < 2; nb++)
                    #pragma unroll
                    for (int e = 0; e < 4; e++) acc[mb][nb][e] = 0.0f;

            #pragma unroll
            for (int kc = 0; kc < 8; kc++) {
                const int chunk = kc * 2 + ksel;
                uint32_t ah[2][4], al[2][4], bh[4], bl[4];
                #pragma unroll
                for (int mb = 0; mb < 2; mb++) {
                    uint32_t off = (uint32_t)((chunk ^ a7[mb]) << 4);
                    ldsm4(ah[mb], A_OFF + aRel[mb] + off);
                    ldsm4(al[mb], A_OFF + 16384u + aRel[mb] + off);
                }
                {
                    uint32_t off = (uint32_t)((chunk ^ b7) << 4);
                    ldsm4(bh, bufB + bOff + off);
                    ldsm4(bl, bufB + 16384u + bOff + off);
                }
                #pragma unroll
                for (int mb = 0; mb < 2; mb++) {
                    mma_bf16(acc[mb][0], ah[mb], bh[0], bh[2]);
                    mma_bf16(acc[mb][1], ah[mb], bh[1], bh[3]);
                    mma_bf16(acc[mb][0], ah[mb], bl[0], bl[2]);
                    mma_bf16(acc[mb][1], ah[mb], bl[1], bl[3]);
                    mma_bf16(acc[mb][0], al[mb], bh[0], bh[2]);
                    mma_bf16(acc[mb][1], al[mb], bh[1], bh[3]);
                }
            }

            // ---- two-sided mining epilogue (meta from 4-slot ring; the only
            // writer during this window targets slot (t+2)&3, distance 2)
            const unsigned char* metaS = smem + SM_META + ((t & 3) * 512);
            #pragma unroll
            for (int nb = 0; nb < 2; nb++) {
                int idx = wx * 16 + nb * 8 + (lane & 3) * 2;
                float2 sq2  = *(const float2*)(metaS + idx * 4);
                int2   lab2 = *(const int2*)(metaS + 256 + idx * 4);
                float cp0 = -BIGF, cn0 = BIGF, cp1 = -BIGF, cn1 = BIGF;
                #pragma unroll
                for (int mb = 0; mb < 2; mb++) {
                    const int h0 = mb * 2, h1 = mb * 2 + 1;
                    float m00 = fmaf(acc[mb][nb][0], -2.0f, sq2.x);
                    float m01 = fmaf(acc[mb][nb][1], -2.0f, sq2.y);
                    float m10 = fmaf(acc[mb][nb][2], -2.0f, sq2.x);
                    float m11 = fmaf(acc[mb][nb][3], -2.0f, sq2.y);
                    bool e00 = (lab2.x == labi[h0]);
                    bool e01 = (lab2.y == labi[h0]);
                    bool e10 = (lab2.x == labi[h1]);
                    bool e11 = (lab2.y == labi[h1]);
                    if (e00) pmm[h0] = fmaxf(pmm[h0], m00); else nmm[h0] = fminf(nmm[h0], m00);
                    if (e01) pmm[h0] = fmaxf(pmm[h0], m01); else nmm[h0] = fminf(nmm[h0], m01);
                    if (e10) pmm[h1] = fmaxf(pmm[h1], m10); else nmm[h1] = fminf(nmm[h1], m10);
                    if (e11) pmm[h1] = fmaxf(pmm[h1], m11); else nmm[h1] = fminf(nmm[h1], m11);
                    float d00 = m00 + sqi[h0], d01 = m01 + sqi[h0];
                    float d10 = m10 + sqi[h1], d11 = m11 + sqi[h1];
                    if (e00) cp0 = fmaxf(cp0, d00); else cn0 = fminf(cn0, d00);
                    if (e01) cp1 = fmaxf(cp1, d01); else cn1 = fminf(cn1, d01);
                    if (e10) cp0 = fmaxf(cp0, d10); else cn0 = fminf(cn0, d10);
                    if (e11) cp1 = fmaxf(cp1, d11); else cn1 = fminf(cn1, d11);
                }
                #pragma unroll
                for (int m = 4; m <= 16; m <<= 1) {
                    cp0 = fmaxf(cp0, __shfl_xor_sync(0xFFFFFFFFu, cp0, m));
                    cn0 = fminf(cn0, __shfl_xor_sync(0xFFFFFFFFu, cn0, m));
                    cp1 = fmaxf(cp1, __shfl_xor_sync(0xFFFFFFFFu, cp1, m));
                    cn1 = fminf(cn1, __shfl_xor_sync(0xFFFFFFFFu, cn1, m));
                }
                if (lane < 4) {
                    int j0 = jBase + wx * 16 + nb * 8 + lane * 2;
                    atomicMax(&g_pos[j0],     __float_as_int(cp0));
                    atomicMin(&g_neg[j0],     __float_as_int(cn0));
                    atomicMax(&g_pos[j0 + 1], __float_as_int(cp1));
                    atomicMin(&g_neg[j0 + 1], __float_as_int(cn1));
                }
            }

            // single sync point per tile (same proof as the 128x128 version)
            if (t + 1 < len) {
                cp_wait<0>();
                __syncthreads();
                if (t + 2 < len) {
                    load_tileB(B_OFF + (t & 1) * 32768, M_OFF, (t + 2) & 3,
                               (tj0 + t + 2) * BT, tid);
                    cp_commit();
                }
            }
        }
        __syncthreads();                   // smem quiescent before next segment

        // row-side flush for this segment
        #pragma unroll
        for (int mb = 0; mb < 2; mb++) {
            #pragma unroll
            for (int h = 0; h < 2; h++) {
                int q = mb * 2 + h;
                float p = sqi[q] + pmm[q];
                float n = sqi[q] + nmm[q];
                p = fmaxf(p, __shfl_xor_sync(0xFFFFFFFFu, p, 1));
                p = fmaxf(p, __shfl_xor_sync(0xFFFFFFFFu, p, 2));
                n = fminf(n, __shfl_xor_sync(0xFFFFFFFFu, n, 1));
                n = fminf(n, __shfl_xor_sync(0xFFFFFFFFu, n, 2));
                if ((lane & 3) == 0) {
                    int row = iBase + wy * 32 + mb * 16 + (lane >> 2) + h * 8;
                    atomicMax(&g_pos[row], __float_as_int(p));
                    atomicMin(&g_neg[row], __float_as_int(n));
                }
            }
        }

        f += len;
    }
}

// ---------------- final reduction: FIN_BLOCKS x 512, atomic partials ----------
__global__ void final_kernel(float* __restrict__ out) {
    int tid = threadIdx.x, lane = tid & 31, wrp = tid >> 5;
    int i = blockIdx.x * 512 + tid;
    float s = 0.0f, c = 0.0f;
    float p = __int_as_float(g_pos[i]);
    float n = __int_as_float(g_neg[i]);
    if (p > 1e-2f && n < 1e29f) {
        s = fmaxf(sqrtf(p) - sqrtf(fmaxf(n, 0.0f)) + MARGIN, 0.0f);
        c = 1.0f;
    }
    #pragma unroll
    for (int m = 16; m; m >>= 1) {
        s += __shfl_xor_sync(0xFFFFFFFFu, s, m);
        c += __shfl_xor_sync(0xFFFFFFFFu, c, m);
    }
    __shared__ float red[32];
    if (lane == 0) { red[wrp] = s; red[16 + wrp] = c; }
    __syncthreads();
    if (wrp == 0) {
        s = (lane < 16) ? red[lane] : 0.0f;
        c = (lane < 16) ? red[16 + lane] : 0.0f;
        #pragma unroll
        for (int m = 8; m; m >>= 1) {
            s += __shfl_xor_sync(0xFFFFFFFFu, s, m);
            c += __shfl_xor_sync(0xFFFFFFFFu, c, m);
        }
        if (lane == 0) {
            atomicAdd(&g_sum, s);
            atomicAdd(&g_cnt, c);
            __threadfence();
            if (atomicAdd(&g_done, 1) == FIN_BLOCKS - 1) {
                float S = atomicAdd(&g_sum, 0.0f);
                float C = atomicAdd(&g_cnt, 0.0f);
                out[0] = (C > 0.0f) ? (S / C) : 0.0f;
            }
        }
    }
}

// ---------------- launch ----------------
extern "C" void kernel_launch(void* const* d_in, const int* in_sizes, int n_in,
                              void* d_out, int out_size) {
    const float* emb = (const float*)d_in[0];
    const int*   lab = (const int*)d_in[1];

    cudaFuncSetAttribute(main_kernel, cudaFuncAttributeMaxDynamicSharedMemorySize, SM_TOTAL);

    prep_kernel<<<N_PTS * 32 / 256, 256>>>(emb, lab);
    main_kernel<<<GRID_MAIN, NTHREADS, SM_TOTAL>>>();
    final_kernel<<<FIN_BLOCKS, 512>>>((float*)d_out);
}